// round 14
// baseline (speedup 1.0000x reference)
#include <cuda_runtime.h>
#include <cuda_bf16.h>
#include <stdint.h>

// LSTM B=128,T=1024,D=512,H=512. Phase 1: xW=obs@Wi parallel GEMM (bf16x3).
// Phase 2: persistent recurrence h@Wh (K=512), grid 128, 512 threads:
// warps 0-7 compute k 0-255, warps 8-15 k 256-511 (private staging + half-barriers),
// smem accumulator reduction, group 0 owns c-state/epilogue/global barrier.
#define SWZ(x) ((x) ^ (((x) >> 3) & 0x70))

__device__ __align__(128) unsigned short g_obs_hi[67108864];  // [t][b][d]
__device__ __align__(128) unsigned short g_obs_lo[67108864];
__device__ __align__(128) unsigned char  g_wt[8388608];       // [htile 64][hi 64KB | lo 64KB]
__device__ __align__(128) unsigned short g_hh[2][65536];
__device__ __align__(128) unsigned short g_hl[2][65536];
__device__ __align__(128) float g_xw[268435456];              // [t][hj][b 128][n 32]
__device__ volatile unsigned g_sense;
__device__ unsigned g_count;

__device__ __forceinline__ uint32_t smem_u32(const void* p) {
    uint32_t a;
    asm("{ .reg .u64 t; cvta.to.shared.u64 t, %1; cvt.u32.u64 %0, t; }" : "=r"(a) : "l"(p));
    return a;
}
#define CPA(d, s) asm volatile("cp.async.cg.shared.global [%0], [%1], 16;" :: "r"(d), "l"(s) : "memory")
#define CPCOMMIT() asm volatile("cp.async.commit_group;" ::: "memory")
#define CPWAIT(n)  asm volatile("cp.async.wait_group %0;" :: "n"(n) : "memory")
#define BARS(id, cnt) asm volatile("bar.sync %0, %1;" :: "r"(id), "r"(cnt) : "memory")
#define LDM4(r, a) \
    asm volatile("ldmatrix.sync.aligned.m8n8.x4.shared.b16 {%0,%1,%2,%3}, [%4];" \
        : "=r"((r)[0]), "=r"((r)[1]), "=r"((r)[2]), "=r"((r)[3]) : "r"(a) : "memory")
#define LDM4T(r, a) \
    asm volatile("ldmatrix.sync.aligned.m8n8.x4.trans.shared.b16 {%0,%1,%2,%3}, [%4];" \
        : "=r"((r)[0]), "=r"((r)[1]), "=r"((r)[2]), "=r"((r)[3]) : "r"(a) : "memory")
#define MMA(d, a, b0, b1) \
    asm volatile("mma.sync.aligned.m16n8k16.row.col.f32.bf16.bf16.f32 " \
        "{%0,%1,%2,%3},{%4,%5,%6,%7},{%8,%9},{%0,%1,%2,%3};" \
        : "+f"((d)[0]), "+f"((d)[1]), "+f"((d)[2]), "+f"((d)[3]) \
        : "r"((a)[0]), "r"((a)[1]), "r"((a)[2]), "r"((a)[3]), "r"(b0), "r"(b1))

__device__ __forceinline__ void bsplit(float v, unsigned short& h, unsigned short& l) {
    __nv_bfloat16 bh = __float2bfloat16(v);
    __nv_bfloat16 bl = __float2bfloat16(v - __bfloat162float(bh));
    h = *(unsigned short*)&bh; l = *(unsigned short*)&bl;
}
__device__ __forceinline__ int nloc(int j, int g) {
    return ((j >> 2) << 4) | ((g >> 1) << 3) | ((j & 3) << 1) | (g & 1);
}

// ---------------- prep ----------------
__global__ void pack_w(const float* __restrict__ Wi, const float* __restrict__ Wh) {
    int c = blockIdx.x;
    unsigned char* base = g_wt + (size_t)c * 131072;
    for (int e = threadIdx.x; e < 32768; e += 256) {
        int k = e >> 5, n = e & 31;
        int g = 2 * ((n >> 3) & 1) + (n & 1);
        int j = (n >> 4) * 4 + ((n >> 1) & 3);
        int col = g * 512 + c * 8 + j;
        float v = (k < 512) ? Wi[k * 2048 + col] : Wh[(k - 512) * 2048 + col];
        unsigned short h, l; bsplit(v, h, l);
        int off = k * 64 + ((((n >> 3)) ^ ((k >> 1) & 3)) << 4) + ((n & 7) << 1);
        *(unsigned short*)(base + off) = h;
        *(unsigned short*)(base + 65536 + off) = l;
    }
}
__global__ void conv_obs(const float* __restrict__ obs) {
    size_t g = (size_t)blockIdx.x * 256 + threadIdx.x;
    int d4 = (int)(g & 127); size_t bt = g >> 7;
    int b = (int)(bt >> 10), t = (int)(bt & 1023);
    float4 v = *(const float4*)&obs[(((size_t)b * 1024 + t) * 512) + d4 * 4];
    unsigned short h0,h1,h2,h3,l0,l1,l2,l3;
    bsplit(v.x,h0,l0); bsplit(v.y,h1,l1); bsplit(v.z,h2,l2); bsplit(v.w,h3,l3);
    size_t o = ((size_t)t * 128 + b) * 512 + d4 * 4;
    *(ushort4*)&g_obs_hi[o] = make_ushort4(h0,h1,h2,h3);
    *(ushort4*)&g_obs_lo[o] = make_ushort4(l0,l1,l2,l3);
}
__global__ void pack_h0(const float* __restrict__ h0p) {
    int g = blockIdx.x * 256 + threadIdx.x;
    unsigned short h, l; bsplit(h0p[g], h, l);
    g_hh[0][g] = h; g_hl[0][g] = l;
}

// stage one [64 rows][64 k] hi+lo sub-chunk into a 16KB buffer (256 threads, tloc 0..255)
__device__ __forceinline__ void stage64(uint32_t dst, const unsigned short* hi,
                                        const unsigned short* lo, int row0, int koff, int tloc) {
    #pragma unroll
    for (int i = 0; i < 2; i++) {
        int g = i * 256 + tloc; int r = g >> 3, seg = g & 7;
        uint32_t d = dst + SWZ(r * 128 + seg * 16);
        size_t s = (size_t)(row0 + r) * 512 + koff + seg * 8;
        CPA(d, hi + s);
        CPA(d + 8192, lo + s);
    }
}

// ---------------- phase 1: xW = obs@Wi (unchanged) ----------------
__global__ void __launch_bounds__(256, 1) gemm_xw() {
    extern __shared__ char sm[];   // [Wi hi 32K | lo 32K][A: 4 x 16K]
    const int tid = threadIdx.x, warp = tid >> 5, lane = tid & 31;
    const int hj = blockIdx.x & 63, bi = (blockIdx.x >> 6) & 1, tg = blockIdx.x >> 7;
    const int row0 = bi * 64;
    const uint32_t smW = smem_u32(sm), smA = smW + 65536;

    const unsigned char* wsrc = g_wt + (size_t)hj * 131072;
    for (int i = tid; i < 2048; i += 256) {
        CPA(smW + i * 16, wsrc + i * 16);
        CPA(smW + 32768 + i * 16, wsrc + 65536 + i * 16);
    }
    CPCOMMIT(); CPWAIT(0);
    __syncthreads();

    const int wr = warp & 3, wn = warp >> 2;
    const int m0 = wr * 16, j = wn * 4 + (lane & 3);
    const int rA = row0 + m0 + (lane >> 2);
    const int arow = m0 + (lane & 15), hseg = (lane >> 4) * 16;
    const int brow_l = lane & 15, bgsel = lane >> 4;
    const int nb = nloc(j, 0);
    const int t0 = tg * 128;

    stage64(smA, g_obs_hi + (size_t)t0 * 65536, g_obs_lo + (size_t)t0 * 65536, row0, 0, tid); CPCOMMIT();
    stage64(smA + 16384, g_obs_hi + (size_t)t0 * 65536, g_obs_lo + (size_t)t0 * 65536, row0, 64, tid); CPCOMMIT();

    for (int it = 0; it < 128; it++) {
        const int t = t0 + it;
        float acc0[4] = {0,0,0,0}, acc1[4] = {0,0,0,0};
        for (int ch = 0; ch < 8; ch++) {
            CPWAIT(1);
            __syncthreads();
            int gi2 = it * 8 + ch + 2;
            if (gi2 < 1024) {
                int t2 = t0 + (gi2 >> 3), c2 = gi2 & 7;
                stage64(smA + (gi2 & 3) * 16384, g_obs_hi + (size_t)t2 * 65536,
                        g_obs_lo + (size_t)t2 * 65536, row0, c2 * 64, tid);
            }
            CPCOMMIT();
            const uint32_t Ab = smA + (ch & 3) * 16384;
            #pragma unroll
            for (int ks = 0; ks < 4; ks++) {
                uint32_t ah[4], al[4], bh[4], bl[4];
                uint32_t aoff = Ab + SWZ(arow * 128 + ks * 32 + hseg);
                LDM4(ah, aoff); LDM4(al, aoff + 8192);
                int krow = ch * 64 + ks * 16 + brow_l;
                uint32_t ba = smW + krow * 64 + (((wn * 2 + bgsel) ^ ((krow >> 1) & 3)) << 4);
                LDM4T(bh, ba); LDM4T(bl, ba + 32768);
                MMA(acc0, ah, bh[0], bh[1]); MMA(acc1, ah, bh[2], bh[3]);
                MMA(acc0, ah, bl[0], bl[1]); MMA(acc1, ah, bl[2], bl[3]);
                MMA(acc0, al, bh[0], bh[1]); MMA(acc1, al, bh[2], bh[3]);
            }
        }
        #pragma unroll
        for (int rh = 0; rh < 2; rh++) {
            size_t base = ((size_t)(t * 64 + hj) * 128 + rA + rh * 8) * 32;
            g_xw[base + nb]     = acc0[2 * rh + 0];
            g_xw[base + nb + 1] = acc0[2 * rh + 1];
            g_xw[base + nb + 8] = acc1[2 * rh + 0];
            g_xw[base + nb + 9] = acc1[2 * rh + 1];
        }
    }
}

// ---------------- phase 2: recurrence (h@Wh, K split across 2 warp groups) ----------------
__global__ void __launch_bounds__(512, 1) lstm_rec(
    const float* __restrict__ bv, const float* __restrict__ c0,
    float* __restrict__ out, int out_size)
{
    extern __shared__ char sm[];  // [Wh hi 32K|lo 32K][A: 8 x 16K][xw 2 x 8K][Y 8K]
    const int tid = threadIdx.x, warp = tid >> 5, lane = tid & 31;
    const int grp = warp >> 3, wl = warp & 7, tloc = tid & 255;
    const int bi = blockIdx.x >> 6, hj = blockIdx.x & 63;
    const int row0 = bi * 64, hc0 = hj * 8;
    const uint32_t smW = smem_u32(sm), smA = smW + 65536, smX = smA + 131072;
    float* Yb = (float*)(sm + 212992);

    const unsigned char* wsrc = g_wt + (size_t)hj * 131072;
    for (int i = tid; i < 2048; i += 512) {
        CPA(smW + i * 16, wsrc + 32768 + i * 16);             // Wh hi
        CPA(smW + 32768 + i * 16, wsrc + 98304 + i * 16);     // Wh lo
    }
    CPCOMMIT(); CPWAIT(0);
    __syncthreads();

    const int wr = wl & 3, wn = wl >> 2;
    const int m0 = wr * 16, j = wn * 4 + (lane & 3);
    const int rA = row0 + m0 + (lane >> 2);
    const int arow = m0 + (lane & 15), hseg = (lane >> 4) * 16;
    const int brow_l = lane & 15, bgsel = lane >> 4;
    const int nb = nloc(j, 0);
    const int rl0 = m0 + (lane >> 2);
    const int yi = (wl * 32 + lane) * 8;

    float b_i = 0.f, b_f = 0.f, b_g = 0.f, b_o = 0.f, cs0 = 0.f, cs1 = 0.f;
    if (grp == 0) {
        b_i = bv[0 * 512 + hc0 + j]; b_f = bv[1 * 512 + hc0 + j];
        b_g = bv[2 * 512 + hc0 + j]; b_o = bv[3 * 512 + hc0 + j];
        cs0 = c0[(size_t)rA * 512 + hc0 + j];
        cs1 = c0[(size_t)(rA + 8) * 512 + hc0 + j];
        // prefetch xw tile for t=0 (joins grp0's first commit group)
        const float* xs = g_xw + ((size_t)(0 * 64 + hj) * 128 + row0) * 32 + tloc * 8;
        CPA(smX + tloc * 32, xs);
        CPA(smX + tloc * 32 + 16, xs + 4);
    }

    const uint32_t qb = smA + grp * 65536;   // this group's 4 sub-chunk buffers
    const int koff0 = grp * 256;

    for (int t = 0; t < 1024; t++) {
        const unsigned short* hh = g_hh[t & 1];
        const unsigned short* hl = g_hl[t & 1];
        // stage own K-half in 2 commit groups (quarters overlap with MMA below)
        stage64(qb,         hh, hl, row0, koff0,       tloc);
        stage64(qb + 16384, hh, hl, row0, koff0 + 64,  tloc);
        CPCOMMIT();
        stage64(qb + 32768, hh, hl, row0, koff0 + 128, tloc);
        stage64(qb + 49152, hh, hl, row0, koff0 + 192, tloc);
        CPCOMMIT();

        float acc0[4] = {0,0,0,0}, acc1[4] = {0,0,0,0};

        CPWAIT(1);
        BARS(1 + grp, 256);
        #pragma unroll
        for (int ks = 0; ks < 8; ks++) {
            const int ksg = grp * 16 + ks;
            uint32_t ah[4], al[4], bh[4], bl[4];
            uint32_t aoff = smA + (ksg >> 2) * 16384 + SWZ(arow * 128 + (ksg & 3) * 32 + hseg);
            LDM4(ah, aoff); LDM4(al, aoff + 8192);
            int krow = ksg * 16 + brow_l;
            uint32_t ba = smW + krow * 64 + (((wn * 2 + bgsel) ^ ((krow >> 1) & 3)) << 4);
            LDM4T(bh, ba); LDM4T(bl, ba + 32768);
            MMA(acc0, ah, bh[0], bh[1]); MMA(acc1, ah, bh[2], bh[3]);
            MMA(acc0, ah, bl[0], bl[1]); MMA(acc1, ah, bl[2], bl[3]);
            MMA(acc0, al, bh[0], bh[1]); MMA(acc1, al, bh[2], bh[3]);
        }
        CPWAIT(0);
        BARS(1 + grp, 256);
        #pragma unroll
        for (int ks = 8; ks < 16; ks++) {
            const int ksg = grp * 16 + ks;
            uint32_t ah[4], al[4], bh[4], bl[4];
            uint32_t aoff = smA + (ksg >> 2) * 16384 + SWZ(arow * 128 + (ksg & 3) * 32 + hseg);
            LDM4(ah, aoff); LDM4(al, aoff + 8192);
            int krow = ksg * 16 + brow_l;
            uint32_t ba = smW + krow * 64 + (((wn * 2 + bgsel) ^ ((krow >> 1) & 3)) << 4);
            LDM4T(bh, ba); LDM4T(bl, ba + 32768);
            MMA(acc0, ah, bh[0], bh[1]); MMA(acc1, ah, bh[2], bh[3]);
            MMA(acc0, ah, bl[0], bl[1]); MMA(acc1, ah, bl[2], bl[3]);
            MMA(acc0, al, bh[0], bh[1]); MMA(acc1, al, bh[2], bh[3]);
        }

        // reduction: grp1 publishes partials, grp0 combines + epilogue
        if (grp == 1) {
            *(float4*)&Yb[yi]     = make_float4(acc0[0], acc0[1], acc0[2], acc0[3]);
            *(float4*)&Yb[yi + 4] = make_float4(acc1[0], acc1[1], acc1[2], acc1[3]);
        }
        __syncthreads();
        if (grp == 0) {
            float4 y0 = *(const float4*)&Yb[yi];
            float4 y1 = *(const float4*)&Yb[yi + 4];
            acc0[0] += y0.x; acc0[1] += y0.y; acc0[2] += y0.z; acc0[3] += y0.w;
            acc1[0] += y1.x; acc1[1] += y1.y; acc1[2] += y1.z; acc1[3] += y1.w;

            const float* smXf = (const float*)(sm + 196608 + (t & 1) * 8192);
            const int pn = (t + 1) & 1;
            #pragma unroll
            for (int rh = 0; rh < 2; rh++) {
                const int r = rA + rh * 8;
                const int xb = (rl0 + rh * 8) * 32;
                float iv = acc0[2 * rh + 0] + smXf[xb + nb]     + b_i;
                float fv = acc0[2 * rh + 1] + smXf[xb + nb + 1] + b_f;
                float gv = acc1[2 * rh + 0] + smXf[xb + nb + 8] + b_g;
                float ov = acc1[2 * rh + 1] + smXf[xb + nb + 9] + b_o;
                float si = 1.f / (1.f + __expf(-iv));
                float sf = 1.f / (1.f + __expf(-fv));
                float so = 1.f / (1.f + __expf(-ov));
                float tg = 1.f - 2.f / (__expf(2.f * gv) + 1.f);
                float cn = sf * (rh ? cs1 : cs0) + si * tg;
                if (rh) cs1 = cn; else cs0 = cn;
                float tc = 1.f - 2.f / (__expf(2.f * cn) + 1.f);
                float hv = so * tc;
                out[((size_t)r * 1024 + t) * 512 + hc0 + j] = hv;
                unsigned short hb, lb; bsplit(hv, hb, lb);
                g_hh[pn][r * 512 + hc0 + j] = hb;
                g_hl[pn][r * 512 + hc0 + j] = lb;
                if (t == 1023 && out_size >= 67108864 + 131072) {
                    out[67108864 + r * 512 + hc0 + j] = cn;
                    out[67108864 + 65536 + r * 512 + hc0 + j] = hv;
                }
            }
            // prefetch next step's xw tile (joins grp0's next first commit group)
            if (t + 1 < 1024) {
                const float* xs = g_xw + ((size_t)((t + 1) * 64 + hj) * 128 + row0) * 32 + tloc * 8;
                uint32_t xd = smX + ((t + 1) & 1) * 8192 + tloc * 32;
                CPA(xd, xs);
                CPA(xd + 16, xs + 4);
            }
        }

        __threadfence();
        __syncthreads();
        if (tid == 0) {
            const unsigned target = (unsigned)((t & 1) ^ 1);
            if (atomicAdd(&g_count, 1u) == 127) {
                g_count = 0; __threadfence(); g_sense = target;
            } else {
                while (g_sense != target) { } __threadfence();
            }
        }
        __syncthreads();
    }
}

extern "C" void kernel_launch(void* const* d_in, const int* in_sizes, int n_in,
                              void* d_out, int out_size)
{
    const float* obs = (const float*)d_in[0];
    const float* Wi  = (const float*)d_in[1];
    const float* Wh  = (const float*)d_in[2];
    const float* bv  = (const float*)d_in[3];
    const float* c0  = (const float*)d_in[4];
    const float* h0  = (const float*)d_in[5];

    pack_w<<<64, 256>>>(Wi, Wh);
    conv_obs<<<65536, 256>>>(obs);
    pack_h0<<<256, 256>>>(h0);

    const int smem_g = 131072;   // 64K W + 64K A
    cudaFuncSetAttribute(gemm_xw, cudaFuncAttributeMaxDynamicSharedMemorySize, smem_g);
    gemm_xw<<<1024, 256, smem_g>>>();

    const int smem_r = 221184;   // 64K W + 128K A + 16K xw + 8K Y
    cudaFuncSetAttribute(lstm_rec, cudaFuncAttributeMaxDynamicSharedMemorySize, smem_r);
    lstm_rec<<<128, 512, smem_r>>>(bv, c0, (float*)d_out, out_size);
}

// round 15
// speedup vs baseline: 1.0608x; 1.0608x over previous
#include <cuda_runtime.h>
#include <cuda_bf16.h>
#include <cuda_fp16.h>
#include <stdint.h>

// LSTM B=128,T=1024,D=512,H=512. Phase 1: xW=obs@Wi parallel GEMM (bf16x3).
// Phase 2: persistent recurrence h@Wh (K=512), fp16 2-term (Wh single fp16,
// h split fp16 hi/lo): 3 ldmatrix + 4 MMA per k16. Per-batch-half barriers.
#define SWZ(x) ((x) ^ (((x) >> 3) & 0x70))

__device__ __align__(128) unsigned short g_obs_hi[67108864];  // [t][b][d] bf16
__device__ __align__(128) unsigned short g_obs_lo[67108864];
__device__ __align__(128) unsigned char  g_wt[8388608];       // bf16 Wi [htile][hi|lo]
__device__ __align__(128) unsigned short g_wf[1048576];       // fp16 Wh [htile][k 512][n 32]
__device__ __align__(128) unsigned short g_hh[2][65536];      // fp16 h hi
__device__ __align__(128) unsigned short g_hl[2][65536];      // fp16 h lo
__device__ __align__(128) float g_xw[268435456];              // [t][hj][b 128][n 32]
__device__ volatile unsigned g_sense2[2];
__device__ unsigned g_count2[2];

__device__ __forceinline__ uint32_t smem_u32(const void* p) {
    uint32_t a;
    asm("{ .reg .u64 t; cvta.to.shared.u64 t, %1; cvt.u32.u64 %0, t; }" : "=r"(a) : "l"(p));
    return a;
}
#define CPA(d, s) asm volatile("cp.async.cg.shared.global [%0], [%1], 16;" :: "r"(d), "l"(s) : "memory")
#define CPCOMMIT() asm volatile("cp.async.commit_group;" ::: "memory")
#define CPWAIT(n)  asm volatile("cp.async.wait_group %0;" :: "n"(n) : "memory")
#define LDM4(r, a) \
    asm volatile("ldmatrix.sync.aligned.m8n8.x4.shared.b16 {%0,%1,%2,%3}, [%4];" \
        : "=r"((r)[0]), "=r"((r)[1]), "=r"((r)[2]), "=r"((r)[3]) : "r"(a) : "memory")
#define LDM4T(r, a) \
    asm volatile("ldmatrix.sync.aligned.m8n8.x4.trans.shared.b16 {%0,%1,%2,%3}, [%4];" \
        : "=r"((r)[0]), "=r"((r)[1]), "=r"((r)[2]), "=r"((r)[3]) : "r"(a) : "memory")
#define MMA(d, a, b0, b1) \
    asm volatile("mma.sync.aligned.m16n8k16.row.col.f32.bf16.bf16.f32 " \
        "{%0,%1,%2,%3},{%4,%5,%6,%7},{%8,%9},{%0,%1,%2,%3};" \
        : "+f"((d)[0]), "+f"((d)[1]), "+f"((d)[2]), "+f"((d)[3]) \
        : "r"((a)[0]), "r"((a)[1]), "r"((a)[2]), "r"((a)[3]), "r"(b0), "r"(b1))
#define MMAH(d, a, b0, b1) \
    asm volatile("mma.sync.aligned.m16n8k16.row.col.f32.f16.f16.f32 " \
        "{%0,%1,%2,%3},{%4,%5,%6,%7},{%8,%9},{%0,%1,%2,%3};" \
        : "+f"((d)[0]), "+f"((d)[1]), "+f"((d)[2]), "+f"((d)[3]) \
        : "r"((a)[0]), "r"((a)[1]), "r"((a)[2]), "r"((a)[3]), "r"(b0), "r"(b1))

__device__ __forceinline__ void bsplit(float v, unsigned short& h, unsigned short& l) {
    __nv_bfloat16 bh = __float2bfloat16(v);
    __nv_bfloat16 bl = __float2bfloat16(v - __bfloat162float(bh));
    h = *(unsigned short*)&bh; l = *(unsigned short*)&bl;
}
__device__ __forceinline__ void hsplit(float v, unsigned short& h, unsigned short& l) {
    __half hh = __float2half(v);
    __half hl = __float2half(v - __half2float(hh));
    h = *(unsigned short*)&hh; l = *(unsigned short*)&hl;
}
__device__ __forceinline__ int nloc(int j, int g) {
    return ((j >> 2) << 4) | ((g >> 1) << 3) | ((j & 3) << 1) | (g & 1);
}

// ---------------- prep ----------------
__global__ void pack_w(const float* __restrict__ Wi, const float* __restrict__ Wh) {
    int c = blockIdx.x;
    unsigned char* base = g_wt + (size_t)c * 131072;
    for (int e = threadIdx.x; e < 16384; e += 256) {
        int k = e >> 5, n = e & 31;       // k 0..511
        int g = 2 * ((n >> 3) & 1) + (n & 1);
        int j = (n >> 4) * 4 + ((n >> 1) & 3);
        int col = g * 512 + c * 8 + j;
        int off = k * 64 + (((n >> 3) ^ ((k >> 1) & 3)) << 4) + ((n & 7) << 1);
        // bf16 hi/lo of Wi (for gemm_xw)
        unsigned short h, l; bsplit(Wi[k * 2048 + col], h, l);
        *(unsigned short*)(base + off) = h;
        *(unsigned short*)(base + 65536 + off) = l;
        // fp16 of Wh (for recurrence)
        __half wh = __float2half(Wh[k * 2048 + col]);
        g_wf[(size_t)c * 16384 + (off >> 1)] = *(unsigned short*)&wh;
    }
}
__global__ void conv_obs(const float* __restrict__ obs) {
    size_t g = (size_t)blockIdx.x * 256 + threadIdx.x;
    int d4 = (int)(g & 127); size_t bt = g >> 7;
    int b = (int)(bt >> 10), t = (int)(bt & 1023);
    float4 v = *(const float4*)&obs[(((size_t)b * 1024 + t) * 512) + d4 * 4];
    unsigned short h0,h1,h2,h3,l0,l1,l2,l3;
    bsplit(v.x,h0,l0); bsplit(v.y,h1,l1); bsplit(v.z,h2,l2); bsplit(v.w,h3,l3);
    size_t o = ((size_t)t * 128 + b) * 512 + d4 * 4;
    *(ushort4*)&g_obs_hi[o] = make_ushort4(h0,h1,h2,h3);
    *(ushort4*)&g_obs_lo[o] = make_ushort4(l0,l1,l2,l3);
}
__global__ void pack_h0(const float* __restrict__ h0p) {
    int g = blockIdx.x * 256 + threadIdx.x;
    unsigned short h, l; hsplit(h0p[g], h, l);
    g_hh[0][g] = h; g_hl[0][g] = l;
}

// stage one [64 rows][64 k] hi+lo sub-chunk into a 16KB buffer
__device__ __forceinline__ void stage64(uint32_t dst, const unsigned short* hi,
                                        const unsigned short* lo, int row0, int koff, int tloc) {
    #pragma unroll
    for (int i = 0; i < 2; i++) {
        int g = i * 256 + tloc; int r = g >> 3, seg = g & 7;
        uint32_t d = dst + SWZ(r * 128 + seg * 16);
        size_t s = (size_t)(row0 + r) * 512 + koff + seg * 8;
        CPA(d, hi + s);
        CPA(d + 8192, lo + s);
    }
}

// ---------------- phase 1: xW = obs@Wi (bf16x3, unchanged) ----------------
__global__ void __launch_bounds__(256, 1) gemm_xw() {
    extern __shared__ char sm[];   // [Wi hi 32K | lo 32K][A: 4 x 16K]
    const int tid = threadIdx.x, warp = tid >> 5, lane = tid & 31;
    const int hj = blockIdx.x & 63, bi = (blockIdx.x >> 6) & 1, tg = blockIdx.x >> 7;
    const int row0 = bi * 64;
    const uint32_t smW = smem_u32(sm), smA = smW + 65536;

    const unsigned char* wsrc = g_wt + (size_t)hj * 131072;
    for (int i = tid; i < 2048; i += 256) {
        CPA(smW + i * 16, wsrc + i * 16);
        CPA(smW + 32768 + i * 16, wsrc + 65536 + i * 16);
    }
    CPCOMMIT(); CPWAIT(0);
    __syncthreads();

    const int wr = warp & 3, wn = warp >> 2;
    const int m0 = wr * 16, j = wn * 4 + (lane & 3);
    const int rA = row0 + m0 + (lane >> 2);
    const int arow = m0 + (lane & 15), hseg = (lane >> 4) * 16;
    const int brow_l = lane & 15, bgsel = lane >> 4;
    const int nb = nloc(j, 0);
    const int t0 = tg * 128;

    stage64(smA, g_obs_hi + (size_t)t0 * 65536, g_obs_lo + (size_t)t0 * 65536, row0, 0, tid); CPCOMMIT();
    stage64(smA + 16384, g_obs_hi + (size_t)t0 * 65536, g_obs_lo + (size_t)t0 * 65536, row0, 64, tid); CPCOMMIT();

    for (int it = 0; it < 128; it++) {
        const int t = t0 + it;
        float acc0[4] = {0,0,0,0}, acc1[4] = {0,0,0,0};
        for (int ch = 0; ch < 8; ch++) {
            CPWAIT(1);
            __syncthreads();
            int gi2 = it * 8 + ch + 2;
            if (gi2 < 1024) {
                int t2 = t0 + (gi2 >> 3), c2 = gi2 & 7;
                stage64(smA + (gi2 & 3) * 16384, g_obs_hi + (size_t)t2 * 65536,
                        g_obs_lo + (size_t)t2 * 65536, row0, c2 * 64, tid);
            }
            CPCOMMIT();
            const uint32_t Ab = smA + (ch & 3) * 16384;
            #pragma unroll
            for (int ks = 0; ks < 4; ks++) {
                uint32_t ah[4], al[4], bh[4], bl[4];
                uint32_t aoff = Ab + SWZ(arow * 128 + ks * 32 + hseg);
                LDM4(ah, aoff); LDM4(al, aoff + 8192);
                int krow = ch * 64 + ks * 16 + brow_l;
                uint32_t ba = smW + krow * 64 + (((wn * 2 + bgsel) ^ ((krow >> 1) & 3)) << 4);
                LDM4T(bh, ba); LDM4T(bl, ba + 32768);
                MMA(acc0, ah, bh[0], bh[1]); MMA(acc1, ah, bh[2], bh[3]);
                MMA(acc0, ah, bl[0], bl[1]); MMA(acc1, ah, bl[2], bl[3]);
                MMA(acc0, al, bh[0], bh[1]); MMA(acc1, al, bh[2], bh[3]);
            }
        }
        #pragma unroll
        for (int rh = 0; rh < 2; rh++) {
            size_t base = ((size_t)(t * 64 + hj) * 128 + rA + rh * 8) * 32;
            g_xw[base + nb]     = acc0[2 * rh + 0];
            g_xw[base + nb + 1] = acc0[2 * rh + 1];
            g_xw[base + nb + 8] = acc1[2 * rh + 0];
            g_xw[base + nb + 9] = acc1[2 * rh + 1];
        }
    }
}

// ---------------- phase 2: recurrence (h@Wh, fp16 2-term) ----------------
__global__ void __launch_bounds__(256, 1) lstm_rec(
    const float* __restrict__ bv, const float* __restrict__ c0,
    float* __restrict__ out, int out_size)
{
    extern __shared__ char sm[];  // [Wh fp16 32K][A: 8 x 16K][xw 2 x 8K]
    const int tid = threadIdx.x, warp = tid >> 5, lane = tid & 31;
    const int bi = blockIdx.x >> 6, hj = blockIdx.x & 63;
    const int row0 = bi * 64, hc0 = hj * 8;
    const uint32_t smW = smem_u32(sm), smA = smW + 32768, smX = smA + 131072;

    const unsigned char* wfsrc = (const unsigned char*)(g_wf + (size_t)hj * 16384);
    for (int i = tid; i < 2048; i += 256) CPA(smW + i * 16, wfsrc + i * 16);
    CPCOMMIT(); CPWAIT(0);
    __syncthreads();

    const int wr = warp & 3, wn = warp >> 2;
    const int m0 = wr * 16, j = wn * 4 + (lane & 3);
    const int rA = row0 + m0 + (lane >> 2);
    const int arow = m0 + (lane & 15), hseg = (lane >> 4) * 16;
    const int brow_l = lane & 15, bgsel = lane >> 4;
    const int nb = nloc(j, 0);
    const int rl0 = m0 + (lane >> 2);

    float b_i = bv[0 * 512 + hc0 + j], b_f = bv[1 * 512 + hc0 + j];
    float b_g = bv[2 * 512 + hc0 + j], b_o = bv[3 * 512 + hc0 + j];
    float cs0 = c0[(size_t)rA * 512 + hc0 + j];
    float cs1 = c0[(size_t)(rA + 8) * 512 + hc0 + j];

    // prefetch xw tile for t=0 (joins the first commit group of t=0)
    {
        const float* xs = g_xw + ((size_t)(0 * 64 + hj) * 128 + row0) * 32 + tid * 8;
        CPA(smX + tid * 32, xs);
        CPA(smX + tid * 32 + 16, xs + 4);
    }

    for (int t = 0; t < 1024; t++) {
        const unsigned short* hh = g_hh[t & 1];
        const unsigned short* hl = g_hl[t & 1];
        stage64(smA,         hh, hl, row0, 0,   tid);
        stage64(smA + 16384, hh, hl, row0, 64,  tid);
        stage64(smA + 32768, hh, hl, row0, 128, tid);
        stage64(smA + 49152, hh, hl, row0, 192, tid);
        CPCOMMIT();                                   // group1: k 0..255 (+pending xw)
        stage64(smA + 65536,  hh, hl, row0, 256, tid);
        stage64(smA + 81920,  hh, hl, row0, 320, tid);
        stage64(smA + 98304,  hh, hl, row0, 384, tid);
        stage64(smA + 114688, hh, hl, row0, 448, tid);
        CPCOMMIT();                                   // group2: k 256..511

        float acc0[4] = {0,0,0,0}, acc1[4] = {0,0,0,0};

        CPWAIT(1);
        __syncthreads();
        #pragma unroll
        for (int ks = 0; ks < 16; ks++) {
            uint32_t ah[4], al[4], b[4];
            uint32_t aoff = smA + (ks >> 2) * 16384 + SWZ(arow * 128 + (ks & 3) * 32 + hseg);
            LDM4(ah, aoff); LDM4(al, aoff + 8192);
            int krow = ks * 16 + brow_l;
            uint32_t ba = smW + krow * 64 + (((wn * 2 + bgsel) ^ ((krow >> 1) & 3)) << 4);
            LDM4T(b, ba);
            MMAH(acc0, ah, b[0], b[1]); MMAH(acc1, ah, b[2], b[3]);
            MMAH(acc0, al, b[0], b[1]); MMAH(acc1, al, b[2], b[3]);
        }
        CPWAIT(0);
        __syncthreads();
        #pragma unroll
        for (int ks = 16; ks < 32; ks++) {
            uint32_t ah[4], al[4], b[4];
            uint32_t aoff = smA + (ks >> 2) * 16384 + SWZ(arow * 128 + (ks & 3) * 32 + hseg);
            LDM4(ah, aoff); LDM4(al, aoff + 8192);
            int krow = ks * 16 + brow_l;
            uint32_t ba = smW + krow * 64 + (((wn * 2 + bgsel) ^ ((krow >> 1) & 3)) << 4);
            LDM4T(b, ba);
            MMAH(acc0, ah, b[0], b[1]); MMAH(acc1, ah, b[2], b[3]);
            MMAH(acc0, al, b[0], b[1]); MMAH(acc1, al, b[2], b[3]);
        }

        // epilogue: gates; publish fp16 h first (critical path), defer fp32 out
        const float* smXf = (const float*)(sm + 163840 + (t & 1) * 8192);
        const int pn = (t + 1) & 1;
        float hv0, hv1;
        #pragma unroll
        for (int rh = 0; rh < 2; rh++) {
            const int r = rA + rh * 8;
            const int xb = (rl0 + rh * 8) * 32;
            float iv = acc0[2 * rh + 0] + smXf[xb + nb]     + b_i;
            float fv = acc0[2 * rh + 1] + smXf[xb + nb + 1] + b_f;
            float gv = acc1[2 * rh + 0] + smXf[xb + nb + 8] + b_g;
            float ov = acc1[2 * rh + 1] + smXf[xb + nb + 9] + b_o;
            float si = 1.f / (1.f + __expf(-iv));
            float sf = 1.f / (1.f + __expf(-fv));
            float so = 1.f / (1.f + __expf(-ov));
            float tg = 1.f - 2.f / (__expf(2.f * gv) + 1.f);
            float cn = sf * (rh ? cs1 : cs0) + si * tg;
            if (rh) cs1 = cn; else cs0 = cn;
            float tc = 1.f - 2.f / (__expf(2.f * cn) + 1.f);
            float hv = so * tc;
            if (rh) hv1 = hv; else hv0 = hv;
            unsigned short hb, lb; hsplit(hv, hb, lb);
            g_hh[pn][r * 512 + hc0 + j] = hb;
            g_hl[pn][r * 512 + hc0 + j] = lb;
        }
        // prefetch next step's xw tile (barrier-independent)
        if (t + 1 < 1024) {
            const float* xs = g_xw + ((size_t)((t + 1) * 64 + hj) * 128 + row0) * 32 + tid * 8;
            uint32_t xd = smX + ((t + 1) & 1) * 8192 + tid * 32;
            CPA(xd, xs);
            CPA(xd + 16, xs + 4);
        }

        // per-batch-half barrier (64 CTAs each)
        __threadfence();
        __syncthreads();
        if (tid == 0) {
            const unsigned target = (unsigned)((t & 1) ^ 1);
            if (atomicAdd(&g_count2[bi], 1u) == 63) {
                g_count2[bi] = 0; __threadfence(); g_sense2[bi] = target;
            } else {
                while (g_sense2[bi] != target) { } __threadfence();
            }
        }
        __syncthreads();

        // deferred fp32 output stores (off critical path)
        out[((size_t)rA * 1024 + t) * 512 + hc0 + j] = hv0;
        out[((size_t)(rA + 8) * 1024 + t) * 512 + hc0 + j] = hv1;
        if (t == 1023 && out_size >= 67108864 + 131072) {
            out[67108864 + rA * 512 + hc0 + j] = cs0;
            out[67108864 + (rA + 8) * 512 + hc0 + j] = cs1;
            out[67108864 + 65536 + rA * 512 + hc0 + j] = hv0;
            out[67108864 + 65536 + (rA + 8) * 512 + hc0 + j] = hv1;
        }
    }
}

extern "C" void kernel_launch(void* const* d_in, const int* in_sizes, int n_in,
                              void* d_out, int out_size)
{
    const float* obs = (const float*)d_in[0];
    const float* Wi  = (const float*)d_in[1];
    const float* Wh  = (const float*)d_in[2];
    const float* bv  = (const float*)d_in[3];
    const float* c0  = (const float*)d_in[4];
    const float* h0  = (const float*)d_in[5];

    pack_w<<<64, 256>>>(Wi, Wh);
    conv_obs<<<65536, 256>>>(obs);
    pack_h0<<<256, 256>>>(h0);

    const int smem_g = 131072;   // 64K W + 64K A
    cudaFuncSetAttribute(gemm_xw, cudaFuncAttributeMaxDynamicSharedMemorySize, smem_g);
    gemm_xw<<<1024, 256, smem_g>>>();

    const int smem_r = 180224;   // 32K W + 128K A + 16K xw
    cudaFuncSetAttribute(lstm_rec, cudaFuncAttributeMaxDynamicSharedMemorySize, smem_r);
    lstm_rec<<<128, 256, smem_r>>>(bv, c0, (float*)d_out, out_size);
}

// round 16
// speedup vs baseline: 1.3230x; 1.2472x over previous
#include <cuda_runtime.h>
#include <cuda_fp16.h>
#include <stdint.h>

// LSTM B=128,T=1024,D=512,H=512. All-fp16 operands (error budget: ~1e-4 vs 1e-3 gate).
// Phase 1: xW=obs@Wi parallel GEMM, 2 ldm + 2 MMA per k16.
// Phase 2: persistent recurrence h@Wh (K=512), grid 128, single-fp16 h.
#define SWZ(x) ((x) ^ (((x) >> 3) & 0x70))

__device__ __align__(128) unsigned short g_obs[67108864];   // fp16 [t][b][d]
__device__ __align__(128) unsigned short g_wif[1048576];    // fp16 Wi [htile][k 512][n 32]
__device__ __align__(128) unsigned short g_wf[1048576];     // fp16 Wh [htile][k 512][n 32]
__device__ __align__(128) unsigned short g_hh[2][65536];    // fp16 h [phase][b][h]
__device__ __align__(128) float g_xw[268435456];            // [t][hj][b 128][n 32]
__device__ volatile unsigned g_sense2[2];
__device__ unsigned g_count2[2];

__device__ __forceinline__ uint32_t smem_u32(const void* p) {
    uint32_t a;
    asm("{ .reg .u64 t; cvta.to.shared.u64 t, %1; cvt.u32.u64 %0, t; }" : "=r"(a) : "l"(p));
    return a;
}
#define CPA(d, s) asm volatile("cp.async.cg.shared.global [%0], [%1], 16;" :: "r"(d), "l"(s) : "memory")
#define CPCOMMIT() asm volatile("cp.async.commit_group;" ::: "memory")
#define CPWAIT(n)  asm volatile("cp.async.wait_group %0;" :: "n"(n) : "memory")
#define LDM4(r, a) \
    asm volatile("ldmatrix.sync.aligned.m8n8.x4.shared.b16 {%0,%1,%2,%3}, [%4];" \
        : "=r"((r)[0]), "=r"((r)[1]), "=r"((r)[2]), "=r"((r)[3]) : "r"(a) : "memory")
#define LDM4T(r, a) \
    asm volatile("ldmatrix.sync.aligned.m8n8.x4.trans.shared.b16 {%0,%1,%2,%3}, [%4];" \
        : "=r"((r)[0]), "=r"((r)[1]), "=r"((r)[2]), "=r"((r)[3]) : "r"(a) : "memory")
#define MMAH(d, a, b0, b1) \
    asm volatile("mma.sync.aligned.m16n8k16.row.col.f32.f16.f16.f32 " \
        "{%0,%1,%2,%3},{%4,%5,%6,%7},{%8,%9},{%0,%1,%2,%3};" \
        : "+f"((d)[0]), "+f"((d)[1]), "+f"((d)[2]), "+f"((d)[3]) \
        : "r"((a)[0]), "r"((a)[1]), "r"((a)[2]), "r"((a)[3]), "r"(b0), "r"(b1))

__device__ __forceinline__ int nloc(int j, int g) {
    return ((j >> 2) << 4) | ((g >> 1) << 3) | ((j & 3) << 1) | (g & 1);
}

// ---------------- prep ----------------
__global__ void pack_w(const float* __restrict__ Wi, const float* __restrict__ Wh) {
    int c = blockIdx.x;
    for (int e = threadIdx.x; e < 16384; e += 256) {
        int k = e >> 5, n = e & 31;       // k 0..511
        int g = 2 * ((n >> 3) & 1) + (n & 1);
        int j = (n >> 4) * 4 + ((n >> 1) & 3);
        int col = g * 512 + c * 8 + j;
        int off = (k * 64 + (((n >> 3) ^ ((k >> 1) & 3)) << 4) + ((n & 7) << 1)) >> 1;
        __half wi = __float2half(Wi[k * 2048 + col]);
        __half wh = __float2half(Wh[k * 2048 + col]);
        g_wif[(size_t)c * 16384 + off] = *(unsigned short*)&wi;
        g_wf[(size_t)c * 16384 + off]  = *(unsigned short*)&wh;
    }
}
__global__ void conv_obs(const float* __restrict__ obs) {
    size_t g = (size_t)blockIdx.x * 256 + threadIdx.x;   // 16,777,216
    int d4 = (int)(g & 127); size_t bt = g >> 7;
    int b = (int)(bt >> 10), t = (int)(bt & 1023);
    float4 v = *(const float4*)&obs[(((size_t)b * 1024 + t) * 512) + d4 * 4];
    __half h0 = __float2half(v.x), h1 = __float2half(v.y);
    __half h2 = __float2half(v.z), h3 = __float2half(v.w);
    size_t o = ((size_t)t * 128 + b) * 512 + d4 * 4;
    *(ushort4*)&g_obs[o] = make_ushort4(*(unsigned short*)&h0, *(unsigned short*)&h1,
                                        *(unsigned short*)&h2, *(unsigned short*)&h3);
}
__global__ void pack_h0(const float* __restrict__ h0p) {
    int g = blockIdx.x * 256 + threadIdx.x;
    __half h = __float2half(h0p[g]);
    g_hh[0][g] = *(unsigned short*)&h;
}

// stage one [64 rows][64 k] fp16 chunk (8KB) into dst
__device__ __forceinline__ void stage64(uint32_t dst, const unsigned short* src,
                                        int row0, int koff, int tloc) {
    #pragma unroll
    for (int i = 0; i < 2; i++) {
        int e = i * 256 + tloc; int r = e >> 3, seg = e & 7;
        uint32_t d = dst + SWZ(r * 128 + seg * 16);
        CPA(d, src + (size_t)(row0 + r) * 512 + koff + seg * 8);
    }
}

// ---------------- phase 1: xW = obs@Wi (fp16 x fp16) ----------------
__global__ void __launch_bounds__(256, 1) gemm_xw() {
    extern __shared__ char sm[];   // [Wi 32K][A: 4 x 8K]
    const int tid = threadIdx.x, warp = tid >> 5, lane = tid & 31;
    const int hj = blockIdx.x & 63, bi = (blockIdx.x >> 6) & 1, tg = blockIdx.x >> 7;
    const int row0 = bi * 64;
    const uint32_t smW = smem_u32(sm), smA = smW + 32768;

    const unsigned char* wsrc = (const unsigned char*)(g_wif + (size_t)hj * 16384);
    for (int i = tid; i < 2048; i += 256) CPA(smW + i * 16, wsrc + i * 16);
    CPCOMMIT(); CPWAIT(0);
    __syncthreads();

    const int wr = warp & 3, wn = warp >> 2;
    const int m0 = wr * 16, j = wn * 4 + (lane & 3);
    const int rA = row0 + m0 + (lane >> 2);
    const int arow = m0 + (lane & 15), hseg = (lane >> 4) * 16;
    const int brow_l = lane & 15, bgsel = lane >> 4;
    const int nb = nloc(j, 0);
    const int t0 = tg * 128;

    stage64(smA, g_obs + (size_t)t0 * 65536, row0, 0, tid); CPCOMMIT();
    stage64(smA + 8192, g_obs + (size_t)t0 * 65536, row0, 64, tid); CPCOMMIT();

    for (int it = 0; it < 128; it++) {
        const int t = t0 + it;
        float acc0[4] = {0,0,0,0}, acc1[4] = {0,0,0,0};
        for (int ch = 0; ch < 8; ch++) {
            CPWAIT(1);
            __syncthreads();
            int gi2 = it * 8 + ch + 2;
            if (gi2 < 1024) {
                int t2 = t0 + (gi2 >> 3), c2 = gi2 & 7;
                stage64(smA + (gi2 & 3) * 8192, g_obs + (size_t)t2 * 65536, row0, c2 * 64, tid);
            }
            CPCOMMIT();
            const uint32_t Ab = smA + (ch & 3) * 8192;
            #pragma unroll
            for (int ks = 0; ks < 4; ks++) {
                uint32_t a[4], b[4];
                LDM4(a, Ab + SWZ(arow * 128 + ks * 32 + hseg));
                int krow = ch * 64 + ks * 16 + brow_l;
                uint32_t ba = smW + krow * 64 + (((wn * 2 + bgsel) ^ ((krow >> 1) & 3)) << 4);
                LDM4T(b, ba);
                MMAH(acc0, a, b[0], b[1]); MMAH(acc1, a, b[2], b[3]);
            }
        }
        #pragma unroll
        for (int rh = 0; rh < 2; rh++) {
            size_t base = ((size_t)(t * 64 + hj) * 128 + rA + rh * 8) * 32;
            g_xw[base + nb]     = acc0[2 * rh + 0];
            g_xw[base + nb + 1] = acc0[2 * rh + 1];
            g_xw[base + nb + 8] = acc1[2 * rh + 0];
            g_xw[base + nb + 9] = acc1[2 * rh + 1];
        }
    }
}

// ---------------- phase 2: recurrence (h@Wh, single fp16) ----------------
__global__ void __launch_bounds__(256, 1) lstm_rec(
    const float* __restrict__ bv, const float* __restrict__ c0,
    float* __restrict__ out, int out_size)
{
    extern __shared__ char sm[];  // [Wh 32K][A: 8 x 8K][xw 2 x 8K]
    const int tid = threadIdx.x, warp = tid >> 5, lane = tid & 31;
    const int bi = blockIdx.x >> 6, hj = blockIdx.x & 63;
    const int row0 = bi * 64, hc0 = hj * 8;
    const uint32_t smW = smem_u32(sm), smA = smW + 32768, smX = smA + 65536;

    const unsigned char* wfsrc = (const unsigned char*)(g_wf + (size_t)hj * 16384);
    for (int i = tid; i < 2048; i += 256) CPA(smW + i * 16, wfsrc + i * 16);
    CPCOMMIT(); CPWAIT(0);
    __syncthreads();

    const int wr = warp & 3, wn = warp >> 2;
    const int m0 = wr * 16, j = wn * 4 + (lane & 3);
    const int rA = row0 + m0 + (lane >> 2);
    const int arow = m0 + (lane & 15), hseg = (lane >> 4) * 16;
    const int brow_l = lane & 15, bgsel = lane >> 4;
    const int nb = nloc(j, 0);
    const int rl0 = m0 + (lane >> 2);

    float b_i = bv[0 * 512 + hc0 + j], b_f = bv[1 * 512 + hc0 + j];
    float b_g = bv[2 * 512 + hc0 + j], b_o = bv[3 * 512 + hc0 + j];
    float cs0 = c0[(size_t)rA * 512 + hc0 + j];
    float cs1 = c0[(size_t)(rA + 8) * 512 + hc0 + j];

    // prefetch xw tile for t=0 (joins the first commit group of t=0)
    {
        const float* xs = g_xw + ((size_t)(0 * 64 + hj) * 128 + row0) * 32 + tid * 8;
        CPA(smX + tid * 32, xs);
        CPA(smX + tid * 32 + 16, xs + 4);
    }

    for (int t = 0; t < 1024; t++) {
        const unsigned short* hh = g_hh[t & 1];
        stage64(smA,         hh, row0, 0,   tid);
        stage64(smA + 8192,  hh, row0, 64,  tid);
        stage64(smA + 16384, hh, row0, 128, tid);
        stage64(smA + 24576, hh, row0, 192, tid);
        CPCOMMIT();                                   // group1: k 0..255 (+pending xw)
        stage64(smA + 32768, hh, row0, 256, tid);
        stage64(smA + 40960, hh, row0, 320, tid);
        stage64(smA + 49152, hh, row0, 384, tid);
        stage64(smA + 57344, hh, row0, 448, tid);
        CPCOMMIT();                                   // group2: k 256..511

        float acc0[4] = {0,0,0,0}, acc1[4] = {0,0,0,0};

        CPWAIT(1);
        __syncthreads();
        #pragma unroll
        for (int ks = 0; ks < 16; ks++) {
            uint32_t a[4], b[4];
            LDM4(a, smA + (ks >> 2) * 8192 + SWZ(arow * 128 + (ks & 3) * 32 + hseg));
            int krow = ks * 16 + brow_l;
            uint32_t ba = smW + krow * 64 + (((wn * 2 + bgsel) ^ ((krow >> 1) & 3)) << 4);
            LDM4T(b, ba);
            MMAH(acc0, a, b[0], b[1]); MMAH(acc1, a, b[2], b[3]);
        }
        CPWAIT(0);
        __syncthreads();
        #pragma unroll
        for (int ks = 16; ks < 32; ks++) {
            uint32_t a[4], b[4];
            LDM4(a, smA + (ks >> 2) * 8192 + SWZ(arow * 128 + (ks & 3) * 32 + hseg));
            int krow = ks * 16 + brow_l;
            uint32_t ba = smW + krow * 64 + (((wn * 2 + bgsel) ^ ((krow >> 1) & 3)) << 4);
            LDM4T(b, ba);
            MMAH(acc0, a, b[0], b[1]); MMAH(acc1, a, b[2], b[3]);
        }

        // epilogue: publish fp16 h first (critical path), defer fp32 out
        const float* smXf = (const float*)(sm + 98304 + (t & 1) * 8192);
        const int pn = (t + 1) & 1;
        float hv0, hv1;
        #pragma unroll
        for (int rh = 0; rh < 2; rh++) {
            const int r = rA + rh * 8;
            const int xb = (rl0 + rh * 8) * 32;
            float iv = acc0[2 * rh + 0] + smXf[xb + nb]     + b_i;
            float fv = acc0[2 * rh + 1] + smXf[xb + nb + 1] + b_f;
            float gv = acc1[2 * rh + 0] + smXf[xb + nb + 8] + b_g;
            float ov = acc1[2 * rh + 1] + smXf[xb + nb + 9] + b_o;
            float si = 1.f / (1.f + __expf(-iv));
            float sf = 1.f / (1.f + __expf(-fv));
            float so = 1.f / (1.f + __expf(-ov));
            float tg = 1.f - 2.f / (__expf(2.f * gv) + 1.f);
            float cn = sf * (rh ? cs1 : cs0) + si * tg;
            if (rh) cs1 = cn; else cs0 = cn;
            float tc = 1.f - 2.f / (__expf(2.f * cn) + 1.f);
            float hv = so * tc;
            if (rh) hv1 = hv; else hv0 = hv;
            __half hb = __float2half(hv);
            g_hh[pn][r * 512 + hc0 + j] = *(unsigned short*)&hb;
        }
        // prefetch next step's xw tile (barrier-independent)
        if (t + 1 < 1024) {
            const float* xs = g_xw + ((size_t)((t + 1) * 64 + hj) * 128 + row0) * 32 + tid * 8;
            uint32_t xd = smX + ((t + 1) & 1) * 8192 + tid * 32;
            CPA(xd, xs);
            CPA(xd + 16, xs + 4);
        }

        // per-batch-half barrier (64 CTAs each)
        __threadfence();
        __syncthreads();
        if (tid == 0) {
            const unsigned target = (unsigned)((t & 1) ^ 1);
            if (atomicAdd(&g_count2[bi], 1u) == 63) {
                g_count2[bi] = 0; __threadfence(); g_sense2[bi] = target;
            } else {
                while (g_sense2[bi] != target) { } __threadfence();
            }
        }
        __syncthreads();

        // deferred fp32 output stores (off critical path)
        out[((size_t)rA * 1024 + t) * 512 + hc0 + j] = hv0;
        out[((size_t)(rA + 8) * 1024 + t) * 512 + hc0 + j] = hv1;
        if (t == 1023 && out_size >= 67108864 + 131072) {
            out[67108864 + rA * 512 + hc0 + j] = cs0;
            out[67108864 + (rA + 8) * 512 + hc0 + j] = cs1;
            out[67108864 + 65536 + rA * 512 + hc0 + j] = hv0;
            out[67108864 + 65536 + (rA + 8) * 512 + hc0 + j] = hv1;
        }
    }
}

extern "C" void kernel_launch(void* const* d_in, const int* in_sizes, int n_in,
                              void* d_out, int out_size)
{
    const float* obs = (const float*)d_in[0];
    const float* Wi  = (const float*)d_in[1];
    const float* Wh  = (const float*)d_in[2];
    const float* bv  = (const float*)d_in[3];
    const float* c0  = (const float*)d_in[4];
    const float* h0  = (const float*)d_in[5];

    pack_w<<<64, 256>>>(Wi, Wh);
    conv_obs<<<65536, 256>>>(obs);
    pack_h0<<<256, 256>>>(h0);

    const int smem_g = 65536;    // 32K W + 32K A
    cudaFuncSetAttribute(gemm_xw, cudaFuncAttributeMaxDynamicSharedMemorySize, smem_g);
    gemm_xw<<<1024, 256, smem_g>>>();

    const int smem_r = 114688;   // 32K W + 64K A + 16K xw
    cudaFuncSetAttribute(lstm_rec, cudaFuncAttributeMaxDynamicSharedMemorySize, smem_r);
    lstm_rec<<<128, 256, smem_r>>>(bv, c0, (float*)d_out, out_size);
}

// round 17
// speedup vs baseline: 1.4309x; 1.0815x over previous
#include <cuda_runtime.h>
#include <cuda_fp16.h>
#include <stdint.h>

// LSTM B=128,T=1024,D=512,H=512. All-fp16 operands.
// Phase 1: xW=obs@Wi parallel GEMM (fp16, 2 ldm + 2 MMA per k16).
// Phase 2: persistent recurrence h@Wh (K=512), grid 128, WARP-PRIVATE staging:
// each warp cp.asyncs its own 16 A-rows + waits its own groups -> no __syncthreads
// between global barrier and epilogue. xw in per-thread ldcg registers.
#define SWZ(x) ((x) ^ (((x) >> 3) & 0x70))

__device__ __align__(128) unsigned short g_obs[67108864];   // fp16 [t][b][d]
__device__ __align__(128) unsigned short g_wif[1048576];    // fp16 Wi [htile][k 512][n 32]
__device__ __align__(128) unsigned short g_wf[1048576];     // fp16 Wh [htile][k 512][n 32]
__device__ __align__(128) unsigned short g_hh[2][65536];    // fp16 h [phase][b][h]
__device__ __align__(128) float g_xw[268435456];            // [t][hj][b 128][n 32]
__device__ volatile unsigned g_sense2[2];
__device__ unsigned g_count2[2];

__device__ __forceinline__ uint32_t smem_u32(const void* p) {
    uint32_t a;
    asm("{ .reg .u64 t; cvta.to.shared.u64 t, %1; cvt.u32.u64 %0, t; }" : "=r"(a) : "l"(p));
    return a;
}
#define CPA(d, s) asm volatile("cp.async.cg.shared.global [%0], [%1], 16;" :: "r"(d), "l"(s) : "memory")
#define CPCOMMIT() asm volatile("cp.async.commit_group;" ::: "memory")
#define CPWAIT(n)  asm volatile("cp.async.wait_group %0;" :: "n"(n) : "memory")
#define LDM4(r, a) \
    asm volatile("ldmatrix.sync.aligned.m8n8.x4.shared.b16 {%0,%1,%2,%3}, [%4];" \
        : "=r"((r)[0]), "=r"((r)[1]), "=r"((r)[2]), "=r"((r)[3]) : "r"(a) : "memory")
#define LDM4T(r, a) \
    asm volatile("ldmatrix.sync.aligned.m8n8.x4.trans.shared.b16 {%0,%1,%2,%3}, [%4];" \
        : "=r"((r)[0]), "=r"((r)[1]), "=r"((r)[2]), "=r"((r)[3]) : "r"(a) : "memory")
#define MMAH(d, a, b0, b1) \
    asm volatile("mma.sync.aligned.m16n8k16.row.col.f32.f16.f16.f32 " \
        "{%0,%1,%2,%3},{%4,%5,%6,%7},{%8,%9},{%0,%1,%2,%3};" \
        : "+f"((d)[0]), "+f"((d)[1]), "+f"((d)[2]), "+f"((d)[3]) \
        : "r"((a)[0]), "r"((a)[1]), "r"((a)[2]), "r"((a)[3]), "r"(b0), "r"(b1))

__device__ __forceinline__ int nloc(int j, int g) {
    return ((j >> 2) << 4) | ((g >> 1) << 3) | ((j & 3) << 1) | (g & 1);
}

// ---------------- prep ----------------
__global__ void pack_w(const float* __restrict__ Wi, const float* __restrict__ Wh) {
    int c = blockIdx.x;
    for (int e = threadIdx.x; e < 16384; e += 256) {
        int k = e >> 5, n = e & 31;       // k 0..511
        int g = 2 * ((n >> 3) & 1) + (n & 1);
        int j = (n >> 4) * 4 + ((n >> 1) & 3);
        int col = g * 512 + c * 8 + j;
        int off = (k * 64 + (((n >> 3) ^ ((k >> 1) & 3)) << 4) + ((n & 7) << 1)) >> 1;
        __half wi = __float2half(Wi[k * 2048 + col]);
        __half wh = __float2half(Wh[k * 2048 + col]);
        g_wif[(size_t)c * 16384 + off] = *(unsigned short*)&wi;
        g_wf[(size_t)c * 16384 + off]  = *(unsigned short*)&wh;
    }
}
__global__ void conv_obs(const float* __restrict__ obs) {
    size_t g = (size_t)blockIdx.x * 256 + threadIdx.x;   // 16,777,216
    int d4 = (int)(g & 127); size_t bt = g >> 7;
    int b = (int)(bt >> 10), t = (int)(bt & 1023);
    float4 v = *(const float4*)&obs[(((size_t)b * 1024 + t) * 512) + d4 * 4];
    __half h0 = __float2half(v.x), h1 = __float2half(v.y);
    __half h2 = __float2half(v.z), h3 = __float2half(v.w);
    size_t o = ((size_t)t * 128 + b) * 512 + d4 * 4;
    *(ushort4*)&g_obs[o] = make_ushort4(*(unsigned short*)&h0, *(unsigned short*)&h1,
                                        *(unsigned short*)&h2, *(unsigned short*)&h3);
}
__global__ void pack_h0(const float* __restrict__ h0p) {
    int g = blockIdx.x * 256 + threadIdx.x;
    __half h = __float2half(h0p[g]);
    g_hh[0][g] = *(unsigned short*)&h;
}

// CTA-wide stage of one [64 rows][64 k] fp16 chunk (8KB) -- used by gemm_xw only
__device__ __forceinline__ void stage64(uint32_t dst, const unsigned short* src,
                                        int row0, int koff, int tloc) {
    #pragma unroll
    for (int i = 0; i < 2; i++) {
        int e = i * 256 + tloc; int r = e >> 3, seg = e & 7;
        uint32_t d = dst + SWZ(r * 128 + seg * 16);
        CPA(d, src + (size_t)(row0 + r) * 512 + koff + seg * 8);
    }
}

// ---------------- phase 1: xW = obs@Wi (fp16 x fp16, unchanged) ----------------
__global__ void __launch_bounds__(256, 1) gemm_xw() {
    extern __shared__ char sm[];   // [Wi 32K][A: 4 x 8K]
    const int tid = threadIdx.x, warp = tid >> 5, lane = tid & 31;
    const int hj = blockIdx.x & 63, bi = (blockIdx.x >> 6) & 1, tg = blockIdx.x >> 7;
    const int row0 = bi * 64;
    const uint32_t smW = smem_u32(sm), smA = smW + 32768;

    const unsigned char* wsrc = (const unsigned char*)(g_wif + (size_t)hj * 16384);
    for (int i = tid; i < 2048; i += 256) CPA(smW + i * 16, wsrc + i * 16);
    CPCOMMIT(); CPWAIT(0);
    __syncthreads();

    const int wr = warp & 3, wn = warp >> 2;
    const int m0 = wr * 16, j = wn * 4 + (lane & 3);
    const int rA = row0 + m0 + (lane >> 2);
    const int arow = m0 + (lane & 15), hseg = (lane >> 4) * 16;
    const int brow_l = lane & 15, bgsel = lane >> 4;
    const int nb = nloc(j, 0);
    const int t0 = tg * 128;

    stage64(smA, g_obs + (size_t)t0 * 65536, row0, 0, tid); CPCOMMIT();
    stage64(smA + 8192, g_obs + (size_t)t0 * 65536, row0, 64, tid); CPCOMMIT();

    for (int it = 0; it < 128; it++) {
        const int t = t0 + it;
        float acc0[4] = {0,0,0,0}, acc1[4] = {0,0,0,0};
        for (int ch = 0; ch < 8; ch++) {
            CPWAIT(1);
            __syncthreads();
            int gi2 = it * 8 + ch + 2;
            if (gi2 < 1024) {
                int t2 = t0 + (gi2 >> 3), c2 = gi2 & 7;
                stage64(smA + (gi2 & 3) * 8192, g_obs + (size_t)t2 * 65536, row0, c2 * 64, tid);
            }
            CPCOMMIT();
            const uint32_t Ab = smA + (ch & 3) * 8192;
            #pragma unroll
            for (int ks = 0; ks < 4; ks++) {
                uint32_t a[4], b[4];
                LDM4(a, Ab + SWZ(arow * 128 + ks * 32 + hseg));
                int krow = ch * 64 + ks * 16 + brow_l;
                uint32_t ba = smW + krow * 64 + (((wn * 2 + bgsel) ^ ((krow >> 1) & 3)) << 4);
                LDM4T(b, ba);
                MMAH(acc0, a, b[0], b[1]); MMAH(acc1, a, b[2], b[3]);
            }
        }
        #pragma unroll
        for (int rh = 0; rh < 2; rh++) {
            size_t base = ((size_t)(t * 64 + hj) * 128 + rA + rh * 8) * 32;
            g_xw[base + nb]     = acc0[2 * rh + 0];
            g_xw[base + nb + 1] = acc0[2 * rh + 1];
            g_xw[base + nb + 8] = acc1[2 * rh + 0];
            g_xw[base + nb + 9] = acc1[2 * rh + 1];
        }
    }
}

// ---------------- phase 2: recurrence (h@Wh, warp-private staging) ----------------
// Each warp stages its own 16 A-rows (16KB: 8 chunks of 16r x 64k) and syncs only
// on its own cp.async groups. No CTA syncs between global barrier and epilogue.
__device__ __forceinline__ void stage_own(uint32_t wbuf, const unsigned short* hh,
                                          int rbase, int lane, int i0) {
    #pragma unroll
    for (int i = i0; i < i0 + 16; i++) {
        int e = i * 32 + lane;
        int ch = e >> 7, rem = e & 127, r = rem >> 3, seg = rem & 7;
        CPA(wbuf + ch * 2048 + SWZ(r * 128 + seg * 16),
            hh + (size_t)(rbase + r) * 512 + ch * 64 + seg * 8);
    }
}

__global__ void __launch_bounds__(256, 1) lstm_rec(
    const float* __restrict__ bv, const float* __restrict__ c0,
    float* __restrict__ out, int out_size)
{
    extern __shared__ char sm[];  // [Wh 32K][A: 8 warps x 16K]
    const int tid = threadIdx.x, warp = tid >> 5, lane = tid & 31;
    const int bi = blockIdx.x >> 6, hj = blockIdx.x & 63;
    const int row0 = bi * 64, hc0 = hj * 8;
    const uint32_t smW = smem_u32(sm);
    const uint32_t wbuf = smW + 32768 + warp * 16384;

    const unsigned char* wfsrc = (const unsigned char*)(g_wf + (size_t)hj * 16384);
    for (int i = tid; i < 2048; i += 256) CPA(smW + i * 16, wfsrc + i * 16);
    CPCOMMIT(); CPWAIT(0);
    __syncthreads();

    const int wr = warp & 3, wn = warp >> 2;
    const int m0 = wr * 16, j = wn * 4 + (lane & 3);
    const int rA = row0 + m0 + (lane >> 2);
    const int rbase = row0 + m0;
    const int arow_l = lane & 15, hseg = (lane >> 4) * 16;
    const int brow_l = lane & 15, bgsel = lane >> 4;
    const int nb = nloc(j, 0);

    float b_i = bv[0 * 512 + hc0 + j], b_f = bv[1 * 512 + hc0 + j];
    float b_g = bv[2 * 512 + hc0 + j], b_o = bv[3 * 512 + hc0 + j];
    float cs0 = c0[(size_t)rA * 512 + hc0 + j];
    float cs1 = c0[(size_t)(rA + 8) * 512 + hc0 + j];

    // xw tiles in registers, double-buffered across steps
    float2 xcur[2][2], xnxt[2][2];
    #pragma unroll
    for (int rh = 0; rh < 2; rh++) {
        size_t base = ((size_t)(0 * 64 + hj) * 128 + rA + rh * 8) * 32;
        xcur[rh][0] = __ldcg((const float2*)&g_xw[base + nb]);
        xcur[rh][1] = __ldcg((const float2*)&g_xw[base + nb + 8]);
    }

    for (int t = 0; t < 1024; t++) {
        const unsigned short* hh = g_hh[t & 1];
        // warp-private staging: own 16 rows, 2 commit groups (k 0..255 | k 256..511)
        stage_own(wbuf, hh, rbase, lane, 0);  CPCOMMIT();
        stage_own(wbuf, hh, rbase, lane, 16); CPCOMMIT();

        float acc0[4] = {0,0,0,0}, acc1[4] = {0,0,0,0};

        CPWAIT(1);   // own group1 done -- no CTA sync needed
        #pragma unroll
        for (int ks = 0; ks < 16; ks++) {
            uint32_t a[4], b[4];
            LDM4(a, wbuf + (ks >> 2) * 2048 + SWZ(arow_l * 128 + (ks & 3) * 32 + hseg));
            int krow = ks * 16 + brow_l;
            uint32_t ba = smW + krow * 64 + (((wn * 2 + bgsel) ^ ((krow >> 1) & 3)) << 4);
            LDM4T(b, ba);
            MMAH(acc0, a, b[0], b[1]); MMAH(acc1, a, b[2], b[3]);
        }
        CPWAIT(0);
        #pragma unroll
        for (int ks = 16; ks < 32; ks++) {
            uint32_t a[4], b[4];
            LDM4(a, wbuf + (ks >> 2) * 2048 + SWZ(arow_l * 128 + (ks & 3) * 32 + hseg));
            int krow = ks * 16 + brow_l;
            uint32_t ba = smW + krow * 64 + (((wn * 2 + bgsel) ^ ((krow >> 1) & 3)) << 4);
            LDM4T(b, ba);
            MMAH(acc0, a, b[0], b[1]); MMAH(acc1, a, b[2], b[3]);
        }

        // epilogue: gates from registers; publish fp16 h
        const int pn = (t + 1) & 1;
        float hv0, hv1;
        #pragma unroll
        for (int rh = 0; rh < 2; rh++) {
            const int r = rA + rh * 8;
            float iv = acc0[2 * rh + 0] + xcur[rh][0].x + b_i;
            float fv = acc0[2 * rh + 1] + xcur[rh][0].y + b_f;
            float gv = acc1[2 * rh + 0] + xcur[rh][1].x + b_g;
            float ov = acc1[2 * rh + 1] + xcur[rh][1].y + b_o;
            float si = 1.f / (1.f + __expf(-iv));
            float sf = 1.f / (1.f + __expf(-fv));
            float so = 1.f / (1.f + __expf(-ov));
            float tg = 1.f - 2.f / (__expf(2.f * gv) + 1.f);
            float cn = sf * (rh ? cs1 : cs0) + si * tg;
            if (rh) cs1 = cn; else cs0 = cn;
            float tc = 1.f - 2.f / (__expf(2.f * cn) + 1.f);
            float hv = so * tc;
            if (rh) hv1 = hv; else hv0 = hv;
            __half hb = __float2half(hv);
            g_hh[pn][r * 512 + hc0 + j] = *(unsigned short*)&hb;
        }
        // prefetch next step's xw into registers (barrier-independent)
        if (t + 1 < 1024) {
            #pragma unroll
            for (int rh = 0; rh < 2; rh++) {
                size_t base = ((size_t)((t + 1) * 64 + hj) * 128 + rA + rh * 8) * 32;
                xnxt[rh][0] = __ldcg((const float2*)&g_xw[base + nb]);
                xnxt[rh][1] = __ldcg((const float2*)&g_xw[base + nb + 8]);
            }
        }

        // per-batch-half barrier (64 CTAs each)
        __threadfence();
        __syncthreads();
        if (tid == 0) {
            const unsigned target = (unsigned)((t & 1) ^ 1);
            if (atomicAdd(&g_count2[bi], 1u) == 63) {
                g_count2[bi] = 0; __threadfence(); g_sense2[bi] = target;
            } else {
                while (g_sense2[bi] != target) { } __threadfence();
            }
        }
        __syncthreads();

        // deferred fp32 output stores (off critical path)
        out[((size_t)rA * 1024 + t) * 512 + hc0 + j] = hv0;
        out[((size_t)(rA + 8) * 1024 + t) * 512 + hc0 + j] = hv1;
        if (t == 1023 && out_size >= 67108864 + 131072) {
            out[67108864 + rA * 512 + hc0 + j] = cs0;
            out[67108864 + (rA + 8) * 512 + hc0 + j] = cs1;
            out[67108864 + 65536 + rA * 512 + hc0 + j] = hv0;
            out[67108864 + 65536 + (rA + 8) * 512 + hc0 + j] = hv1;
        }
        #pragma unroll
        for (int rh = 0; rh < 2; rh++) {
            xcur[rh][0] = xnxt[rh][0];
            xcur[rh][1] = xnxt[rh][1];
        }
    }
}

extern "C" void kernel_launch(void* const* d_in, const int* in_sizes, int n_in,
                              void* d_out, int out_size)
{
    const float* obs = (const float*)d_in[0];
    const float* Wi  = (const float*)d_in[1];
    const float* Wh  = (const float*)d_in[2];
    const float* bv  = (const float*)d_in[3];
    const float* c0  = (const float*)d_in[4];
    const float* h0  = (const float*)d_in[5];

    pack_w<<<64, 256>>>(Wi, Wh);
    conv_obs<<<65536, 256>>>(obs);
    pack_h0<<<256, 256>>>(h0);

    const int smem_g = 65536;    // 32K W + 32K A
    cudaFuncSetAttribute(gemm_xw, cudaFuncAttributeMaxDynamicSharedMemorySize, smem_g);
    gemm_xw<<<1024, 256, smem_g>>>();

    const int smem_r = 163840;   // 32K W + 128K A (8 warp-private bufs)
    cudaFuncSetAttribute(lstm_rec, cudaFuncAttributeMaxDynamicSharedMemorySize, smem_r);
    lstm_rec<<<128, 256, smem_r>>>(bv, c0, (float*)d_out, out_size);
}